// round 16
// baseline (speedup 1.0000x reference)
#include <cuda_runtime.h>
#include <cstdint>

// ---------------------------------------------------------------------------
// B=8192 rows, R=2, K0=3072; tree 3072 ->(f=3) 1024 ->(f=2)... -> 1
// Single fused kernel (R15 k1 + low-register epilogue).
// Main: block = 256 rows x 192-leaf span; cp.async double-buffered x staging;
//   synapse R9 form + levels 0..5 -> K=32 scratch [r][node/4][row][node%4].
// Epilogue: last block per rowblock (atomic counter); thread = row; levels
//   6..10 folded with bounded live state (unroll 2 on the j loop -> <=28 regs
//   on the epilogue path, below the main loop's ~60). Root combine -> out.
// ---------------------------------------------------------------------------

#define NROWS   8192
#define SPAN    192
#define CHUNK   12
#define XSTRIDE 20
#define XBUF    (256 * XSTRIDE)          // floats per buffer

__device__ float g_n32[2 * 8 * NROWS * 4];  // [r][node>>2][row][node&3]
__device__ int   g_cnt[32];                  // per-rowblock arrival counter

struct K1Params {
    const float *x, *ap1, *ap2, *am1, *am2, *g0;
    const float *w0, *b0, *w1, *b1, *w2, *b2, *w3, *b3, *w4, *b4, *w5, *b5;
    const float *w6, *b6, *w7, *b7, *w8, *b8, *w9, *b9, *w10, *b10;
    const float *root_w, *root_b;
    float* out;
};

__device__ __forceinline__ float ex2f(float x) {
    float y; asm("ex2.approx.ftz.f32 %0, %1;" : "=f"(y) : "f"(x)); return y;
}
__device__ __forceinline__ float rcpf(float x) {
    float y; asm("rcp.approx.ftz.f32 %0, %1;" : "=f"(y) : "f"(x)); return y;
}
__device__ __forceinline__ float leaky(float y) {
    return fmaxf(y, 0.01f * y);
}
__device__ __forceinline__ void cpasync16(uint32_t dst_smem, const float* src) {
    asm volatile("cp.async.cg.shared.global [%0], [%1], 16;"
                 :: "r"(dst_smem), "l"(src));
}

__global__ void __launch_bounds__(256, 4) k1_fused(K1Params P)
{
    extern __shared__ __align__(16) float s_x[];   // 2 * XBUF floats (dynamic)
    __shared__ float4 s_pa[2][SPAN];          // a1*L2E, a2*L2E, m1*L2E, m2*L2E
    __shared__ float2 s_gw[2][SPAN];          // g0*5, w0
    __shared__ float  s_b0[2][64], s_w1[2][64], s_b1[2][32], s_w2[2][32],
                      s_b2[2][16], s_w3[2][16], s_b3[2][8],  s_w4[2][8],
                      s_b4[2][4],  s_w5[2][4],  s_b5[2][2];
    __shared__ int    s_last;

    const int tid  = threadIdx.x;
    const int r0   = blockIdx.x * 256;
    const int span = blockIdx.y;
    const int k0   = span * SPAN;
    const int row  = r0 + tid;
    const float L2E = 1.4426950408889634f;

    // ---- stage + prescale synapse params (coalesced per array) ----
    for (int i = tid; i < 2 * SPAN; i += 256) {
        int r = i / SPAN, j = i - r * SPAN;
        int idx = r * 3072 + k0 + j;
        s_pa[r][j] = make_float4(P.ap1[idx] * L2E, P.ap2[idx] * L2E,
                                 P.am1[idx] * L2E, P.am2[idx] * L2E);
        s_gw[r][j] = make_float2(P.g0[idx] * 5.0f, P.w0[idx]);
    }
    if (tid < 128)      { int r=tid>>6, j=tid&63;            s_b0[r][j] = P.b0[r*1024 + span*64 + j]; }
    else                { int u=tid-128, r=u>>6, j=u&63;     s_w1[r][j] = P.w1[r*1024 + span*64 + j]; }
    if (tid < 64)       { int r=tid>>5, j=tid&31;            s_b1[r][j] = P.b1[r*512 + span*32 + j]; }
    else if (tid < 128) { int u=tid-64,  r=u>>5, j=u&31;     s_w2[r][j] = P.w2[r*512 + span*32 + j]; }
    else if (tid < 160) { int u=tid-128, r=u>>4, j=u&15;     s_b2[r][j] = P.b2[r*256 + span*16 + j]; }
    else if (tid < 192) { int u=tid-160, r=u>>4, j=u&15;     s_w3[r][j] = P.w3[r*256 + span*16 + j]; }
    else if (tid < 208) { int u=tid-192, r=u>>3, j=u&7;      s_b3[r][j] = P.b3[r*128 + span*8 + j]; }
    else if (tid < 224) { int u=tid-208, r=u>>3, j=u&7;      s_w4[r][j] = P.w4[r*128 + span*8 + j]; }
    else if (tid < 232) { int u=tid-224, r=u>>2, j=u&3;      s_b4[r][j] = P.b4[r*64 + span*4 + j]; }
    else if (tid < 240) { int u=tid-232, r=u>>2, j=u&3;      s_w5[r][j] = P.w5[r*64 + span*4 + j]; }
    else if (tid < 244) { int u=tid-240, r=u>>1, j=u&1;      s_b5[r][j] = P.b5[r*32 + span*2 + j]; }

    const float* xbase = P.x + (size_t)r0 * 3072 + k0;
    const uint32_t sx_base = (uint32_t)__cvta_generic_to_shared(s_x);

    // prologue: stage chunk 0 into buffer 0
    {
#pragma unroll
        for (int it = 0; it < 3; ++it) {
            int i  = it * 256 + tid;
            int r2 = i / 3, cc = i - r2 * 3;
            cpasync16(sx_base + (r2 * XSTRIDE + cc * 4) * 4,
                      xbase + (size_t)r2 * 3072 + cc * 4);
        }
        asm volatile("cp.async.commit_group;");
    }

    float c3[2], c4[2], c5[2];

#pragma unroll
    for (int g = 0; g < 16; ++g) {            // one 12-leaf group per chunk
        asm volatile("cp.async.wait_group 0;");
        __syncthreads();
        if (g < 15) {
            const int nb = (g + 1) & 1;
#pragma unroll
            for (int it = 0; it < 3; ++it) {
                int i  = it * 256 + tid;
                int r2 = i / 3, cc = i - r2 * 3;
                cpasync16(sx_base + (nb * XBUF + r2 * XSTRIDE + cc * 4) * 4,
                          xbase + (size_t)r2 * 3072 + (g + 1) * CHUNK + cc * 4);
            }
            asm volatile("cp.async.commit_group;");
        }

        const float* buf = s_x + (g & 1) * XBUF;

#pragma unroll
        for (int r = 0; r < 2; ++r) {
            float xs[12];
#pragma unroll
            for (int q = 0; q < 3; ++q) {
                float4 v = *(const float4*)&buf[tid * XSTRIDE + q * 4];
                xs[q*4+0]=v.x; xs[q*4+1]=v.y; xs[q*4+2]=v.z; xs[q*4+3]=v.w;
            }

            float n1[4];
#pragma unroll
            for (int i2 = 0; i2 < 4; ++i2) {
                float acc = s_b0[r][g * 4 + i2];
#pragma unroll
                for (int t = 0; t < 3; ++t) {
                    const int leaf = g * 12 + 3 * i2 + t;
                    float4 pa = s_pa[r][leaf];
                    float2 gw = s_gw[r][leaf];
                    float xv  = xs[3 * i2 + t];
                    float gp  = ex2f(fmaf(pa.x, xv, pa.y));
                    float gm  = ex2f(fmaf(pa.z, xv, pa.w));
                    float den = fmaf(0.2f, gw.x, gp + gm);
                    float num = fmaf(gp, 120.f, gw.x);
                    acc = fmaf(fmaf(num, rcpf(den), -70.f), gw.y, acc);
                }
                n1[i2] = leaky(acc);
            }
            float n2a = leaky(fmaf(n1[1], s_w1[r][4*g+1], fmaf(n1[0], s_w1[r][4*g+0], s_b1[r][2*g+0])));
            float n2b = leaky(fmaf(n1[3], s_w1[r][4*g+3], fmaf(n1[2], s_w1[r][4*g+2], s_b1[r][2*g+1])));
            float v   = leaky(fmaf(n2b,  s_w2[r][2*g+1], fmaf(n2a,  s_w2[r][2*g+0], s_b2[r][g])));

            if ((g & 1) == 0) { c3[r] = v; }
            else {
                const int p3 = g >> 1;
                v = leaky(fmaf(v, s_w3[r][2*p3+1], fmaf(c3[r], s_w3[r][2*p3], s_b3[r][p3])));
                if ((g & 3) == 1) { c4[r] = v; }
                else {
                    const int p4i = g >> 2;
                    v = leaky(fmaf(v, s_w4[r][2*p4i+1], fmaf(c4[r], s_w4[r][2*p4i], s_b4[r][p4i])));
                    if ((g & 7) == 3) { c5[r] = v; }
                    else {
                        const int p5 = g >> 3;
                        v = leaky(fmaf(v, s_w5[r][2*p5+1], fmaf(c5[r], s_w5[r][2*p5], s_b5[r][p5])));
                        const int node = span * 2 + p5;      // 0..31
                        g_n32[(((size_t)(r * 8 + (node >> 2))) << 15)
                              + ((size_t)row << 2) + (node & 3)] = v;
                    }
                }
            }
        }
    }

    // ---- epilogue: last block per rowblock folds levels 6..10 + root ------
    __threadfence();
    __syncthreads();
    if (tid == 0) {
        int old = atomicAdd(&g_cnt[blockIdx.x], 1);
        int last = (old == 15) ? 1 : 0;
        if (last) g_cnt[blockIdx.x] = 0;    // reset for next graph replay
        s_last = last;
    }
    __syncthreads();
    if (!s_last) return;
    __threadfence();

    float y[2];
#pragma unroll
    for (int r = 0; r < 2; ++r) {
        float t[8];
        // bounded live state: unroll 2 -> at most 2 f4 in flight (MLP 2)
#pragma unroll 2
        for (int j = 0; j < 8; ++j) {
            float4 f = *(const float4*)(g_n32 + (((size_t)(r * 8 + j)) << 15)
                                              + ((size_t)row << 2));
            float u0 = leaky(fmaf(f.y, __ldg(P.w6 + r*32 + 4*j + 1),
                             fmaf(f.x, __ldg(P.w6 + r*32 + 4*j),
                                  __ldg(P.b6 + r*16 + 2*j))));
            float u1 = leaky(fmaf(f.w, __ldg(P.w6 + r*32 + 4*j + 3),
                             fmaf(f.z, __ldg(P.w6 + r*32 + 4*j + 2),
                                  __ldg(P.b6 + r*16 + 2*j + 1))));
            t[j] = leaky(fmaf(u1, __ldg(P.w7 + r*16 + 2*j + 1),
                         fmaf(u0, __ldg(P.w7 + r*16 + 2*j),
                              __ldg(P.b7 + r*8 + j))));
        }
#pragma unroll
        for (int n = 0; n < 4; ++n)
            t[n] = leaky(fmaf(t[2*n+1], __ldg(P.w8 + r*8 + 2*n + 1),
                         fmaf(t[2*n],   __ldg(P.w8 + r*8 + 2*n),
                              __ldg(P.b8 + r*4 + n))));
#pragma unroll
        for (int n = 0; n < 2; ++n)
            t[n] = leaky(fmaf(t[2*n+1], __ldg(P.w9 + r*4 + 2*n + 1),
                         fmaf(t[2*n],   __ldg(P.w9 + r*4 + 2*n),
                              __ldg(P.b9 + r*2 + n))));
        y[r] = leaky(fmaf(t[1], __ldg(P.w10 + r*2 + 1),
                     fmaf(t[0], __ldg(P.w10 + r*2),
                          __ldg(P.b10 + r))));
    }
    P.out[row] = fmaf(y[1], __ldg(P.root_w + 1),
                 fmaf(y[0], __ldg(P.root_w), __ldg(P.root_b)));
}

extern "C" void kernel_launch(void* const* d_in, const int* in_sizes, int n_in,
                              void* d_out, int out_size)
{
    const float* w[11];
    const float* b[11];
    bool interleaved = (in_sizes[8] == 2048);
    for (int i = 0; i < 11; ++i) {
        if (interleaved) {
            w[i] = (const float*)d_in[6 + 2 * i];
            b[i] = (const float*)d_in[7 + 2 * i];
        } else {
            w[i] = (const float*)d_in[6 + i];
            b[i] = (const float*)d_in[17 + i];
        }
    }

    static bool attr_set = false;
    if (!attr_set) {
        cudaFuncSetAttribute(k1_fused, cudaFuncAttributeMaxDynamicSharedMemorySize,
                             2 * XBUF * (int)sizeof(float));
        attr_set = true;
    }

    K1Params P1;
    P1.x   = (const float*)d_in[0];
    P1.ap1 = (const float*)d_in[1];
    P1.ap2 = (const float*)d_in[2];
    P1.am1 = (const float*)d_in[3];
    P1.am2 = (const float*)d_in[4];
    P1.g0  = (const float*)d_in[5];
    P1.w0 = w[0]; P1.b0 = b[0];
    P1.w1 = w[1]; P1.b1 = b[1];
    P1.w2 = w[2]; P1.b2 = b[2];
    P1.w3 = w[3]; P1.b3 = b[3];
    P1.w4 = w[4]; P1.b4 = b[4];
    P1.w5 = w[5]; P1.b5 = b[5];
    P1.w6 = w[6]; P1.b6 = b[6];
    P1.w7 = w[7]; P1.b7 = b[7];
    P1.w8 = w[8]; P1.b8 = b[8];
    P1.w9 = w[9]; P1.b9 = b[9];
    P1.w10 = w[10]; P1.b10 = b[10];
    P1.root_w = (const float*)d_in[28];
    P1.root_b = (const float*)d_in[29];
    P1.out    = (float*)d_out;

    k1_fused<<<dim3(32, 16), 256, 2 * XBUF * sizeof(float)>>>(P1);
}

// round 17
// speedup vs baseline: 1.0712x; 1.0712x over previous
#include <cuda_runtime.h>
#include <cstdint>

// ---------------------------------------------------------------------------
// B=8192 rows, R=2, K0=3072; tree 3072 ->(f=3) 1024 ->(f=2)... -> 1
// k1 (R15): block = 256 rows x 192-leaf span; cp.async double-buffered x
//     staging; synapse R9 form + levels 0..5 -> K=32 scratch
//     [r][node/4][row][node%4]. Ends with PDL trigger.
// k2 (R15): thread = (row, r, j); 1 x LDG.128 + levels 6..7; 32 thr fold
//     8..10 + shfl root. Launched via PDL (programmatic dependent launch) so
//     its launch/ramp overlaps k1's tail; opens with grid-dependency sync.
// ---------------------------------------------------------------------------

#define NROWS   8192
#define SPAN    192
#define CHUNK   12
#define XSTRIDE 20
#define XBUF    (256 * XSTRIDE)          // floats per buffer

__device__ float g_n32[2 * 8 * NROWS * 4];  // [r][node>>2][row][node&3]

struct K1Params {
    const float *x, *ap1, *ap2, *am1, *am2, *g0;
    const float *w0, *b0, *w1, *b1, *w2, *b2, *w3, *b3, *w4, *b4, *w5, *b5;
};
struct K2Params {
    const float *w6, *b6, *w7, *b7, *w8, *b8, *w9, *b9, *w10, *b10;
    const float *root_w, *root_b;
    float* out;
};

__device__ __forceinline__ float ex2f(float x) {
    float y; asm("ex2.approx.ftz.f32 %0, %1;" : "=f"(y) : "f"(x)); return y;
}
__device__ __forceinline__ float rcpf(float x) {
    float y; asm("rcp.approx.ftz.f32 %0, %1;" : "=f"(y) : "f"(x)); return y;
}
__device__ __forceinline__ float leaky(float y) {
    return fmaxf(y, 0.01f * y);
}
__device__ __forceinline__ void cpasync16(uint32_t dst_smem, const float* src) {
    asm volatile("cp.async.cg.shared.global [%0], [%1], 16;"
                 :: "r"(dst_smem), "l"(src));
}

__global__ void __launch_bounds__(256, 4) k1_lower(K1Params P)
{
    extern __shared__ __align__(16) float s_x[];   // 2 * XBUF floats (dynamic)
    __shared__ float4 s_pa[2][SPAN];          // a1*L2E, a2*L2E, m1*L2E, m2*L2E
    __shared__ float2 s_gw[2][SPAN];          // g0*5, w0
    __shared__ float  s_b0[2][64], s_w1[2][64], s_b1[2][32], s_w2[2][32],
                      s_b2[2][16], s_w3[2][16], s_b3[2][8],  s_w4[2][8],
                      s_b4[2][4],  s_w5[2][4],  s_b5[2][2];

    const int tid  = threadIdx.x;
    const int r0   = blockIdx.x * 256;
    const int span = blockIdx.y;
    const int k0   = span * SPAN;
    const int row  = r0 + tid;
    const float L2E = 1.4426950408889634f;

    // ---- stage + prescale synapse params (coalesced per array) ----
    for (int i = tid; i < 2 * SPAN; i += 256) {
        int r = i / SPAN, j = i - r * SPAN;
        int idx = r * 3072 + k0 + j;
        s_pa[r][j] = make_float4(P.ap1[idx] * L2E, P.ap2[idx] * L2E,
                                 P.am1[idx] * L2E, P.am2[idx] * L2E);
        s_gw[r][j] = make_float2(P.g0[idx] * 5.0f, P.w0[idx]);
    }
    if (tid < 128)      { int r=tid>>6, j=tid&63;            s_b0[r][j] = P.b0[r*1024 + span*64 + j]; }
    else                { int u=tid-128, r=u>>6, j=u&63;     s_w1[r][j] = P.w1[r*1024 + span*64 + j]; }
    if (tid < 64)       { int r=tid>>5, j=tid&31;            s_b1[r][j] = P.b1[r*512 + span*32 + j]; }
    else if (tid < 128) { int u=tid-64,  r=u>>5, j=u&31;     s_w2[r][j] = P.w2[r*512 + span*32 + j]; }
    else if (tid < 160) { int u=tid-128, r=u>>4, j=u&15;     s_b2[r][j] = P.b2[r*256 + span*16 + j]; }
    else if (tid < 192) { int u=tid-160, r=u>>4, j=u&15;     s_w3[r][j] = P.w3[r*256 + span*16 + j]; }
    else if (tid < 208) { int u=tid-192, r=u>>3, j=u&7;      s_b3[r][j] = P.b3[r*128 + span*8 + j]; }
    else if (tid < 224) { int u=tid-208, r=u>>3, j=u&7;      s_w4[r][j] = P.w4[r*128 + span*8 + j]; }
    else if (tid < 232) { int u=tid-224, r=u>>2, j=u&3;      s_b4[r][j] = P.b4[r*64 + span*4 + j]; }
    else if (tid < 240) { int u=tid-232, r=u>>2, j=u&3;      s_w5[r][j] = P.w5[r*64 + span*4 + j]; }
    else if (tid < 244) { int u=tid-240, r=u>>1, j=u&1;      s_b5[r][j] = P.b5[r*32 + span*2 + j]; }

    const float* xbase = P.x + (size_t)r0 * 3072 + k0;
    const uint32_t sx_base = (uint32_t)__cvta_generic_to_shared(s_x);

    // prologue: stage chunk 0 into buffer 0
    {
#pragma unroll
        for (int it = 0; it < 3; ++it) {
            int i  = it * 256 + tid;
            int r2 = i / 3, cc = i - r2 * 3;
            cpasync16(sx_base + (r2 * XSTRIDE + cc * 4) * 4,
                      xbase + (size_t)r2 * 3072 + cc * 4);
        }
        asm volatile("cp.async.commit_group;");
    }

    float c3[2], c4[2], c5[2];

#pragma unroll
    for (int g = 0; g < 16; ++g) {            // one 12-leaf group per chunk
        asm volatile("cp.async.wait_group 0;");
        __syncthreads();
        if (g < 15) {
            const int nb = (g + 1) & 1;
#pragma unroll
            for (int it = 0; it < 3; ++it) {
                int i  = it * 256 + tid;
                int r2 = i / 3, cc = i - r2 * 3;
                cpasync16(sx_base + (nb * XBUF + r2 * XSTRIDE + cc * 4) * 4,
                          xbase + (size_t)r2 * 3072 + (g + 1) * CHUNK + cc * 4);
            }
            asm volatile("cp.async.commit_group;");
        }

        const float* buf = s_x + (g & 1) * XBUF;

#pragma unroll
        for (int r = 0; r < 2; ++r) {
            float xs[12];
#pragma unroll
            for (int q = 0; q < 3; ++q) {
                float4 v = *(const float4*)&buf[tid * XSTRIDE + q * 4];
                xs[q*4+0]=v.x; xs[q*4+1]=v.y; xs[q*4+2]=v.z; xs[q*4+3]=v.w;
            }

            float n1[4];
#pragma unroll
            for (int i2 = 0; i2 < 4; ++i2) {
                float acc = s_b0[r][g * 4 + i2];
#pragma unroll
                for (int t = 0; t < 3; ++t) {
                    const int leaf = g * 12 + 3 * i2 + t;
                    float4 pa = s_pa[r][leaf];
                    float2 gw = s_gw[r][leaf];
                    float xv  = xs[3 * i2 + t];
                    float gp  = ex2f(fmaf(pa.x, xv, pa.y));
                    float gm  = ex2f(fmaf(pa.z, xv, pa.w));
                    float den = fmaf(0.2f, gw.x, gp + gm);
                    float num = fmaf(gp, 120.f, gw.x);
                    acc = fmaf(fmaf(num, rcpf(den), -70.f), gw.y, acc);
                }
                n1[i2] = leaky(acc);
            }
            float n2a = leaky(fmaf(n1[1], s_w1[r][4*g+1], fmaf(n1[0], s_w1[r][4*g+0], s_b1[r][2*g+0])));
            float n2b = leaky(fmaf(n1[3], s_w1[r][4*g+3], fmaf(n1[2], s_w1[r][4*g+2], s_b1[r][2*g+1])));
            float v   = leaky(fmaf(n2b,  s_w2[r][2*g+1], fmaf(n2a,  s_w2[r][2*g+0], s_b2[r][g])));

            if ((g & 1) == 0) { c3[r] = v; }
            else {
                const int p3 = g >> 1;
                v = leaky(fmaf(v, s_w3[r][2*p3+1], fmaf(c3[r], s_w3[r][2*p3], s_b3[r][p3])));
                if ((g & 3) == 1) { c4[r] = v; }
                else {
                    const int p4i = g >> 2;
                    v = leaky(fmaf(v, s_w4[r][2*p4i+1], fmaf(c4[r], s_w4[r][2*p4i], s_b4[r][p4i])));
                    if ((g & 7) == 3) { c5[r] = v; }
                    else {
                        const int p5 = g >> 3;
                        v = leaky(fmaf(v, s_w5[r][2*p5+1], fmaf(c5[r], s_w5[r][2*p5], s_b5[r][p5])));
                        const int node = span * 2 + p5;      // 0..31
                        g_n32[(((size_t)(r * 8 + (node >> 2))) << 15)
                              + ((size_t)row << 2) + (node & 3)] = v;
                    }
                }
            }
        }
    }

    // PDL: this block's writes are done — let the dependent grid start
    // launching. k2's cudaGridDependencySynchronize() still waits for ALL
    // k1 blocks to complete before consuming g_n32.
    cudaTriggerProgrammaticLaunchCompletion();
}

// ---- k2: thread = (row, r, j); 1 x LDG.128 + levels 6..7, then 8..10 ------
__global__ void __launch_bounds__(256) k2_upper(K2Params P)
{
    __shared__ float s_t[16][17];             // [row16][r*8+j], padded

    // PDL: wait for k1 grid completion (memory visibility included)
    cudaGridDependencySynchronize();

    const int tid   = threadIdx.x;
    const int row16 = tid & 15;
    const int rj    = tid >> 4;               // 0..15
    const int r     = rj & 1;
    const int j     = rj >> 1;                // plane 0..7 (nodes 4j..4j+3)
    const int row   = blockIdx.x * 16 + row16;

    float4 f = *(const float4*)(g_n32 + (((size_t)(r * 8 + j)) << 15)
                                      + ((size_t)row << 2));
    // level 6 (32->16): nodes 2j, 2j+1
    float u0 = leaky(fmaf(f.y, __ldg(P.w6 + r*32 + 4*j + 1),
                     fmaf(f.x, __ldg(P.w6 + r*32 + 4*j),
                          __ldg(P.b6 + r*16 + 2*j))));
    float u1 = leaky(fmaf(f.w, __ldg(P.w6 + r*32 + 4*j + 3),
                     fmaf(f.z, __ldg(P.w6 + r*32 + 4*j + 2),
                          __ldg(P.b6 + r*16 + 2*j + 1))));
    // level 7 (16->8): node j
    s_t[row16][r * 8 + j] = leaky(fmaf(u1, __ldg(P.w7 + r*16 + 2*j + 1),
                                  fmaf(u0, __ldg(P.w7 + r*16 + 2*j),
                                       __ldg(P.b7 + r*8 + j))));
    __syncthreads();

    if (tid < 32) {
        const int rw = tid >> 1;              // row within block
        const int rr = tid & 1;               // repeat
        float t[8];
#pragma unroll
        for (int n = 0; n < 8; ++n) t[n] = s_t[rw][rr * 8 + n];
#pragma unroll
        for (int n = 0; n < 4; ++n)
            t[n] = leaky(fmaf(t[2*n+1], __ldg(P.w8 + rr*8 + 2*n + 1),
                         fmaf(t[2*n],   __ldg(P.w8 + rr*8 + 2*n),
                              __ldg(P.b8 + rr*4 + n))));
#pragma unroll
        for (int n = 0; n < 2; ++n)
            t[n] = leaky(fmaf(t[2*n+1], __ldg(P.w9 + rr*4 + 2*n + 1),
                         fmaf(t[2*n],   __ldg(P.w9 + rr*4 + 2*n),
                              __ldg(P.b9 + rr*2 + n))));
        float y = leaky(fmaf(t[1], __ldg(P.w10 + rr*2 + 1),
                        fmaf(t[0], __ldg(P.w10 + rr*2),
                             __ldg(P.b10 + rr))));

        float yo = __shfl_xor_sync(0xFFFFFFFFu, y, 1);
        if (rr == 0)
            P.out[blockIdx.x * 16 + rw] =
                fmaf(yo, __ldg(P.root_w + 1),
                fmaf(y,  __ldg(P.root_w), __ldg(P.root_b)));
    }
}

extern "C" void kernel_launch(void* const* d_in, const int* in_sizes, int n_in,
                              void* d_out, int out_size)
{
    const float* w[11];
    const float* b[11];
    bool interleaved = (in_sizes[8] == 2048);
    for (int i = 0; i < 11; ++i) {
        if (interleaved) {
            w[i] = (const float*)d_in[6 + 2 * i];
            b[i] = (const float*)d_in[7 + 2 * i];
        } else {
            w[i] = (const float*)d_in[6 + i];
            b[i] = (const float*)d_in[17 + i];
        }
    }

    static bool attr_set = false;
    if (!attr_set) {
        cudaFuncSetAttribute(k1_lower, cudaFuncAttributeMaxDynamicSharedMemorySize,
                             2 * XBUF * (int)sizeof(float));
        attr_set = true;
    }

    K1Params P1;
    P1.x   = (const float*)d_in[0];
    P1.ap1 = (const float*)d_in[1];
    P1.ap2 = (const float*)d_in[2];
    P1.am1 = (const float*)d_in[3];
    P1.am2 = (const float*)d_in[4];
    P1.g0  = (const float*)d_in[5];
    P1.w0 = w[0]; P1.b0 = b[0];
    P1.w1 = w[1]; P1.b1 = b[1];
    P1.w2 = w[2]; P1.b2 = b[2];
    P1.w3 = w[3]; P1.b3 = b[3];
    P1.w4 = w[4]; P1.b4 = b[4];
    P1.w5 = w[5]; P1.b5 = b[5];
    k1_lower<<<dim3(32, 16), 256, 2 * XBUF * sizeof(float)>>>(P1);

    K2Params P2;
    P2.w6 = w[6];  P2.b6 = b[6];
    P2.w7 = w[7];  P2.b7 = b[7];
    P2.w8 = w[8];  P2.b8 = b[8];
    P2.w9 = w[9];  P2.b9 = b[9];
    P2.w10 = w[10]; P2.b10 = b[10];
    P2.root_w = (const float*)d_in[28];
    P2.root_b = (const float*)d_in[29];
    P2.out    = (float*)d_out;

    // PDL launch: k2's launch/ramp overlaps k1's tail
    cudaLaunchConfig_t cfg = {};
    cfg.gridDim  = dim3(512);
    cfg.blockDim = dim3(256);
    cfg.dynamicSmemBytes = 0;
    cfg.stream = 0;
    cudaLaunchAttribute attrs[1];
    attrs[0].id = cudaLaunchAttributeProgrammaticStreamSerialization;
    attrs[0].val.programmaticStreamSerializationAllowed = 1;
    cfg.attrs = attrs;
    cfg.numAttrs = 1;
    cudaLaunchKernelEx(&cfg, k2_upper, P2);
}